// round 10
// baseline (speedup 1.0000x reference)
#include <cuda_runtime.h>
#include <cuda_bf16.h>

#define NHEAD 32
#define DK    8
#define EDIM  256
#define MAXTOK (16 * 4096)

// Scratch (static __device__: no allocation, graph-capture safe).
// Attention output and W, each split into bf16 hi + bf16 lo (residual).
__device__ __nv_bfloat16 g_midh[(size_t)MAXTOK * EDIM];
__device__ __nv_bfloat16 g_midl[(size_t)MAXTOK * EDIM];
__device__ __nv_bfloat16 g_Wh[EDIM * EDIM];
__device__ __nv_bfloat16 g_Wl[EDIM * EDIM];

__device__ __forceinline__ unsigned pack2(float a, float b) {
    __nv_bfloat162 t = __floats2bfloat162_rn(a, b);
    return *reinterpret_cast<unsigned*>(&t);
}
__device__ __forceinline__ float bf16_residual(float v) {
    return v - __bfloat162float(__float2bfloat16_rn(v));
}

// ---------------------------------------------------------------------------
// Kernel 0: W (fp32) -> g_Wh + g_Wl (bf16 split). 65536 elems, 8 per thread.
// ---------------------------------------------------------------------------
__global__ void __launch_bounds__(256) wconv_kernel(const float* __restrict__ W)
{
    const int i = (blockIdx.x * 256 + threadIdx.x) * 8;
    float v[8];
    *reinterpret_cast<float4*>(v)     = *reinterpret_cast<const float4*>(W + i);
    *reinterpret_cast<float4*>(v + 4) = *reinterpret_cast<const float4*>(W + i + 4);
    uint4 h, l;
    h.x = pack2(v[0], v[1]); h.y = pack2(v[2], v[3]);
    h.z = pack2(v[4], v[5]); h.w = pack2(v[6], v[7]);
    l.x = pack2(bf16_residual(v[0]), bf16_residual(v[1]));
    l.y = pack2(bf16_residual(v[2]), bf16_residual(v[3]));
    l.z = pack2(bf16_residual(v[4]), bf16_residual(v[5]));
    l.w = pack2(bf16_residual(v[6]), bf16_residual(v[7]));
    *reinterpret_cast<uint4*>(g_Wh + i) = h;
    *reinterpret_cast<uint4*>(g_Wl + i) = l;
}

// ---------------------------------------------------------------------------
// Kernel 1: per-token quantum attention. TWO tokens per warp, lane = head.
// Single fused pass per g: load q_g once -> dot -> exp -> accumulate.
//   q[h][d] = cos(x[tok,h*8+d] + theta[d])
//   w[g] = exp(q[h].q[g]/sqrt(8))   (|score| <= 2.83 -> no max pass needed)
//   out[h] = sum_g w[g] q[g] / sum_g w[g] -> bf16 hi/lo into g_midh/g_midl
// ---------------------------------------------------------------------------
__global__ void __launch_bounds__(128) attn_kernel(
    const float* __restrict__ x,
    const float* __restrict__ theta,
    int ntok)
{
    __shared__ __align__(16) float qs[4][2][NHEAD][DK];   // 8 KB
    const int wl   = threadIdx.x >> 5;
    const int lane = threadIdx.x & 31;
    const int tok0 = (blockIdx.x * 4 + wl) * 2;
    const int tok1 = tok0 + 1;
    if (tok0 >= ntok) return;              // uniform per warp
    const bool v1 = (tok1 < ntok);

    const float4 th0 = *reinterpret_cast<const float4*>(theta);
    const float4 th1 = *reinterpret_cast<const float4*>(theta + 4);

    float q0[8], q1[8];
    {
        const float4* xp = reinterpret_cast<const float4*>(
            x + (size_t)tok0 * EDIM + lane * DK);
        const float4 a = xp[0], b = xp[1];
        q0[0] = __cosf(a.x + th0.x); q0[1] = __cosf(a.y + th0.y);
        q0[2] = __cosf(a.z + th0.z); q0[3] = __cosf(a.w + th0.w);
        q0[4] = __cosf(b.x + th1.x); q0[5] = __cosf(b.y + th1.y);
        q0[6] = __cosf(b.z + th1.z); q0[7] = __cosf(b.w + th1.w);
    }
    if (v1) {
        const float4* xp = reinterpret_cast<const float4*>(
            x + (size_t)tok1 * EDIM + lane * DK);
        const float4 a = xp[0], b = xp[1];
        q1[0] = __cosf(a.x + th0.x); q1[1] = __cosf(a.y + th0.y);
        q1[2] = __cosf(a.z + th0.z); q1[3] = __cosf(a.w + th0.w);
        q1[4] = __cosf(b.x + th1.x); q1[5] = __cosf(b.y + th1.y);
        q1[6] = __cosf(b.z + th1.z); q1[7] = __cosf(b.w + th1.w);
    } else {
#pragma unroll
        for (int i = 0; i < 8; ++i) q1[i] = 0.f;   // harmless: w=1 everywhere
    }

    *reinterpret_cast<float4*>(&qs[wl][0][lane][0]) = make_float4(q0[0], q0[1], q0[2], q0[3]);
    *reinterpret_cast<float4*>(&qs[wl][0][lane][4]) = make_float4(q0[4], q0[5], q0[6], q0[7]);
    *reinterpret_cast<float4*>(&qs[wl][1][lane][0]) = make_float4(q1[0], q1[1], q1[2], q1[3]);
    *reinterpret_cast<float4*>(&qs[wl][1][lane][4]) = make_float4(q1[4], q1[5], q1[6], q1[7]);
    __syncwarp();

    float ss0 = 0.f, ss1 = 0.f;
    float ac0[8] = {0.f, 0.f, 0.f, 0.f, 0.f, 0.f, 0.f, 0.f};
    float ac1[8] = {0.f, 0.f, 0.f, 0.f, 0.f, 0.f, 0.f, 0.f};

#pragma unroll 8
    for (int g = 0; g < NHEAD; ++g) {
        const float4 a0 = *reinterpret_cast<const float4*>(&qs[wl][0][g][0]);
        const float4 b0 = *reinterpret_cast<const float4*>(&qs[wl][0][g][4]);
        const float4 a1 = *reinterpret_cast<const float4*>(&qs[wl][1][g][0]);
        const float4 b1 = *reinterpret_cast<const float4*>(&qs[wl][1][g][4]);

        const float d0 = q0[0]*a0.x + q0[1]*a0.y + q0[2]*a0.z + q0[3]*a0.w
                       + q0[4]*b0.x + q0[5]*b0.y + q0[6]*b0.z + q0[7]*b0.w;
        const float d1 = q1[0]*a1.x + q1[1]*a1.y + q1[2]*a1.z + q1[3]*a1.w
                       + q1[4]*b1.x + q1[5]*b1.y + q1[6]*b1.z + q1[7]*b1.w;

        const float w0 = __expf(d0 * 0.35355339059327373f);
        const float w1 = __expf(d1 * 0.35355339059327373f);

        ss0 += w0;
        ac0[0] += w0 * a0.x; ac0[1] += w0 * a0.y; ac0[2] += w0 * a0.z; ac0[3] += w0 * a0.w;
        ac0[4] += w0 * b0.x; ac0[5] += w0 * b0.y; ac0[6] += w0 * b0.z; ac0[7] += w0 * b0.w;
        ss1 += w1;
        ac1[0] += w1 * a1.x; ac1[1] += w1 * a1.y; ac1[2] += w1 * a1.z; ac1[3] += w1 * a1.w;
        ac1[4] += w1 * b1.x; ac1[5] += w1 * b1.y; ac1[6] += w1 * b1.z; ac1[7] += w1 * b1.w;
    }

    const float inv0 = 1.0f / ss0;
#pragma unroll
    for (int i = 0; i < 8; ++i) ac0[i] *= inv0;
    {
        uint4 h, l;
        h.x = pack2(ac0[0], ac0[1]); h.y = pack2(ac0[2], ac0[3]);
        h.z = pack2(ac0[4], ac0[5]); h.w = pack2(ac0[6], ac0[7]);
        l.x = pack2(bf16_residual(ac0[0]), bf16_residual(ac0[1]));
        l.y = pack2(bf16_residual(ac0[2]), bf16_residual(ac0[3]));
        l.z = pack2(bf16_residual(ac0[4]), bf16_residual(ac0[5]));
        l.w = pack2(bf16_residual(ac0[6]), bf16_residual(ac0[7]));
        *reinterpret_cast<uint4*>(g_midh + (size_t)tok0 * EDIM + lane * DK) = h;
        *reinterpret_cast<uint4*>(g_midl + (size_t)tok0 * EDIM + lane * DK) = l;
    }
    if (v1) {
        const float inv1 = 1.0f / ss1;
#pragma unroll
        for (int i = 0; i < 8; ++i) ac1[i] *= inv1;
        uint4 h, l;
        h.x = pack2(ac1[0], ac1[1]); h.y = pack2(ac1[2], ac1[3]);
        h.z = pack2(ac1[4], ac1[5]); h.w = pack2(ac1[6], ac1[7]);
        l.x = pack2(bf16_residual(ac1[0]), bf16_residual(ac1[1]));
        l.y = pack2(bf16_residual(ac1[2]), bf16_residual(ac1[3]));
        l.z = pack2(bf16_residual(ac1[4]), bf16_residual(ac1[5]));
        l.w = pack2(bf16_residual(ac1[6]), bf16_residual(ac1[7]));
        *reinterpret_cast<uint4*>(g_midh + (size_t)tok1 * EDIM + lane * DK) = h;
        *reinterpret_cast<uint4*>(g_midl + (size_t)tok1 * EDIM + lane * DK) = l;
    }
}

// ---------------------------------------------------------------------------
// Kernel 2: C = (Ah+Al) @ (Wh+Wl)^T + bias  ~=  Ah Wh^T + Ah Wl^T + Al Wh^T
// via bf16 mma.sync.m16n8k16 (proven path). 3 segments x 8 k-steps.
// ---------------------------------------------------------------------------
#define GBM 128
#define GBN 128
#define GBK 32
#define KSTR 40
#define NSEG 3
#define NKC  (EDIM / GBK)          // 8
#define NIT  (NSEG * NKC)          // 24

__device__ __forceinline__ void mma16816(float* d, const unsigned* a, const unsigned* b) {
    asm volatile(
        "mma.sync.aligned.m16n8k16.row.col.f32.bf16.bf16.f32 "
        "{%0,%1,%2,%3}, {%4,%5,%6,%7}, {%8,%9}, {%0,%1,%2,%3};\n"
        : "+f"(d[0]), "+f"(d[1]), "+f"(d[2]), "+f"(d[3])
        : "r"(a[0]), "r"(a[1]), "r"(a[2]), "r"(a[3]), "r"(b[0]), "r"(b[1]));
}

__global__ void __launch_bounds__(256) gemm_bf16s_kernel(
    const float* __restrict__ bias,
    float* __restrict__ C, int M)
{
    __shared__ __align__(16) __nv_bfloat16 As[GBM][KSTR];
    __shared__ __align__(16) __nv_bfloat16 Bs[GBN][KSTR];

    const int t    = threadIdx.x;
    const int warp = t >> 5;
    const int lane = t & 31;
    const int wm   = warp >> 2;      // 0..1  (M)
    const int wn   = warp & 3;       // 0..3  (N)
    const int gid  = lane >> 2;      // 0..7
    const int tig  = lane & 3;       // 0..3
    const int m0   = blockIdx.x * GBM;
    const int n0   = blockIdx.y * GBN;

    const int lr = t >> 2;           // 0..63 (rows; +64 second pass)
    const int lc = (t & 3) * 8;      // k offset (8 bf16 = 16B chunks)

    // Segment operand tables: Ah*Bh, Ah*Bl, Al*Bh.
    const __nv_bfloat16* aSeg[NSEG] = {
        g_midh + (size_t)m0 * EDIM, g_midh + (size_t)m0 * EDIM, g_midl + (size_t)m0 * EDIM };
    const __nv_bfloat16* bSeg[NSEG] = {
        g_Wh + (size_t)n0 * EDIM, g_Wl + (size_t)n0 * EDIM, g_Wh + (size_t)n0 * EDIM };

    const bool av0 = (m0 + lr) < M;
    const bool av1 = (m0 + lr + 64) < M;

    float acc[4][4][4];
#pragma unroll
    for (int i = 0; i < 4; ++i)
#pragma unroll
        for (int j = 0; j < 4; ++j)
#pragma unroll
            for (int c = 0; c < 4; ++c) acc[i][j][c] = 0.f;

    const uint4 zed = make_uint4(0, 0, 0, 0);
    uint4 aR0, aR1, bR0, bR1;

    {
        const __nv_bfloat16* aB = aSeg[0];
        const __nv_bfloat16* bB = bSeg[0];
        aR0 = av0 ? *reinterpret_cast<const uint4*>(aB + (size_t)lr * EDIM + lc) : zed;
        aR1 = av1 ? *reinterpret_cast<const uint4*>(aB + (size_t)(lr + 64) * EDIM + lc) : zed;
        bR0 = *reinterpret_cast<const uint4*>(bB + (size_t)lr * EDIM + lc);
        bR1 = *reinterpret_cast<const uint4*>(bB + (size_t)(lr + 64) * EDIM + lc);
    }

    for (int it = 0; it < NIT; ++it) {
        *reinterpret_cast<uint4*>(&As[lr][lc])      = aR0;
        *reinterpret_cast<uint4*>(&As[lr + 64][lc]) = aR1;
        *reinterpret_cast<uint4*>(&Bs[lr][lc])      = bR0;
        *reinterpret_cast<uint4*>(&Bs[lr + 64][lc]) = bR1;
        __syncthreads();

        if (it + 1 < NIT) {
            const int nit = it + 1;
            const int seg = nit >> 3;           // /NKC
            const int kc  = (nit & 7) * GBK;
            const __nv_bfloat16* aB = aSeg[seg];
            const __nv_bfloat16* bB = bSeg[seg];
            aR0 = av0 ? *reinterpret_cast<const uint4*>(aB + (size_t)lr * EDIM + kc + lc) : zed;
            aR1 = av1 ? *reinterpret_cast<const uint4*>(aB + (size_t)(lr + 64) * EDIM + kc + lc) : zed;
            bR0 = *reinterpret_cast<const uint4*>(bB + (size_t)lr * EDIM + kc + lc);
            bR1 = *reinterpret_cast<const uint4*>(bB + (size_t)(lr + 64) * EDIM + kc + lc);
        }

#pragma unroll
        for (int ks = 0; ks < 2; ++ks) {
            const int kk = ks * 16 + tig * 2;
            unsigned af[4][4], bf[4][2];
#pragma unroll
            for (int fi = 0; fi < 4; ++fi) {
                const int r = wm * 64 + fi * 16 + gid;
                af[fi][0] = *reinterpret_cast<const unsigned*>(&As[r][kk]);
                af[fi][1] = *reinterpret_cast<const unsigned*>(&As[r + 8][kk]);
                af[fi][2] = *reinterpret_cast<const unsigned*>(&As[r][kk + 8]);
                af[fi][3] = *reinterpret_cast<const unsigned*>(&As[r + 8][kk + 8]);
            }
#pragma unroll
            for (int fj = 0; fj < 4; ++fj) {
                const int r = wn * 32 + fj * 8 + gid;
                bf[fj][0] = *reinterpret_cast<const unsigned*>(&Bs[r][kk]);
                bf[fj][1] = *reinterpret_cast<const unsigned*>(&Bs[r][kk + 8]);
            }
#pragma unroll
            for (int fi = 0; fi < 4; ++fi)
#pragma unroll
                for (int fj = 0; fj < 4; ++fj)
                    mma16816(acc[fi][fj], af[fi], bf[fj]);
        }
        __syncthreads();
    }

#pragma unroll
    for (int fj = 0; fj < 4; ++fj) {
        const int col = n0 + wn * 32 + fj * 8 + tig * 2;
        const float2 bv = *reinterpret_cast<const float2*>(&bias[col]);
#pragma unroll
        for (int fi = 0; fi < 4; ++fi) {
            const int r0 = m0 + wm * 64 + fi * 16 + gid;
            if (r0 < M)
                *reinterpret_cast<float2*>(&C[(size_t)r0 * EDIM + col]) =
                    make_float2(acc[fi][fj][0] + bv.x, acc[fi][fj][1] + bv.y);
            const int r1 = r0 + 8;
            if (r1 < M)
                *reinterpret_cast<float2*>(&C[(size_t)r1 * EDIM + col]) =
                    make_float2(acc[fi][fj][2] + bv.x, acc[fi][fj][3] + bv.y);
        }
    }
}

// ---------------------------------------------------------------------------
// Launch order: attn first (so the profiler capture slot lands on it), then
// wconv, then gemm (depends on both).
// ---------------------------------------------------------------------------
extern "C" void kernel_launch(void* const* d_in, const int* in_sizes, int n_in,
                              void* d_out, int out_size)
{
    const float* x     = (const float*)d_in[0];
    const float* theta = (const float*)d_in[1];
    const float* W     = (const float*)d_in[2];
    const float* bias  = (const float*)d_in[3];
    float* out = (float*)d_out;

    int ntok = in_sizes[0] / EDIM;
    if (ntok > MAXTOK) ntok = MAXTOK;

    attn_kernel<<<(ntok + 7) / 8, 128>>>(x, theta, ntok);
    wconv_kernel<<<EDIM * EDIM / (256 * 8), 256>>>(W);

    dim3 grid((ntok + GBM - 1) / GBM, EDIM / GBN);
    gemm_bf16s_kernel<<<grid, 256>>>(bias, out, ntok);
}

// round 11
// speedup vs baseline: 1.3465x; 1.3465x over previous
#include <cuda_runtime.h>
#include <cuda_fp16.h>

#define NHEAD 32
#define DK    8
#define EDIM  256
#define MAXTOK (16 * 4096)

// Scratch (static __device__: no allocation, graph-capture safe).
// Attention output in single fp16; W split into fp16 hi + fp16 lo residual.
__device__ __half g_mid[(size_t)MAXTOK * EDIM];
__device__ __half g_Wh[EDIM * EDIM];
__device__ __half g_Wl[EDIM * EDIM];

__device__ __forceinline__ unsigned packh2(float a, float b) {
    __half2 t = __floats2half2_rn(a, b);
    return *reinterpret_cast<unsigned*>(&t);
}

// ---------------------------------------------------------------------------
// Kernel 0: W (fp32) -> g_Wh + g_Wl (fp16 split). 65536 elems, 8 per thread.
// ---------------------------------------------------------------------------
__global__ void __launch_bounds__(256) wconv_kernel(const float* __restrict__ W)
{
    const int i = (blockIdx.x * 256 + threadIdx.x) * 8;
    float v[8], r[8];
    *reinterpret_cast<float4*>(v)     = *reinterpret_cast<const float4*>(W + i);
    *reinterpret_cast<float4*>(v + 4) = *reinterpret_cast<const float4*>(W + i + 4);
#pragma unroll
    for (int k = 0; k < 8; ++k)
        r[k] = v[k] - __half2float(__float2half_rn(v[k]));
    uint4 h, l;
    h.x = packh2(v[0], v[1]); h.y = packh2(v[2], v[3]);
    h.z = packh2(v[4], v[5]); h.w = packh2(v[6], v[7]);
    l.x = packh2(r[0], r[1]); l.y = packh2(r[2], r[3]);
    l.z = packh2(r[4], r[5]); l.w = packh2(r[6], r[7]);
    *reinterpret_cast<uint4*>(g_Wh + i) = h;
    *reinterpret_cast<uint4*>(g_Wl + i) = l;
}

// ---------------------------------------------------------------------------
// Kernel 1: per-token quantum attention. TWO tokens per warp, lane = head.
// Single fused pass per g: load q_g once -> dot -> exp -> accumulate.
//   out[h] = sum_g w[g] q[g] / sum_g w[g] -> single fp16 row into g_mid
// ---------------------------------------------------------------------------
__global__ void __launch_bounds__(128) attn_kernel(
    const float* __restrict__ x,
    const float* __restrict__ theta,
    int ntok)
{
    __shared__ __align__(16) float qs[4][2][NHEAD][DK];   // 8 KB
    const int wl   = threadIdx.x >> 5;
    const int lane = threadIdx.x & 31;
    const int tok0 = (blockIdx.x * 4 + wl) * 2;
    const int tok1 = tok0 + 1;
    if (tok0 >= ntok) return;              // uniform per warp
    const bool v1 = (tok1 < ntok);

    const float4 th0 = *reinterpret_cast<const float4*>(theta);
    const float4 th1 = *reinterpret_cast<const float4*>(theta + 4);

    float q0[8], q1[8];
    {
        const float4* xp = reinterpret_cast<const float4*>(
            x + (size_t)tok0 * EDIM + lane * DK);
        const float4 a = xp[0], b = xp[1];
        q0[0] = __cosf(a.x + th0.x); q0[1] = __cosf(a.y + th0.y);
        q0[2] = __cosf(a.z + th0.z); q0[3] = __cosf(a.w + th0.w);
        q0[4] = __cosf(b.x + th1.x); q0[5] = __cosf(b.y + th1.y);
        q0[6] = __cosf(b.z + th1.z); q0[7] = __cosf(b.w + th1.w);
    }
    if (v1) {
        const float4* xp = reinterpret_cast<const float4*>(
            x + (size_t)tok1 * EDIM + lane * DK);
        const float4 a = xp[0], b = xp[1];
        q1[0] = __cosf(a.x + th0.x); q1[1] = __cosf(a.y + th0.y);
        q1[2] = __cosf(a.z + th0.z); q1[3] = __cosf(a.w + th0.w);
        q1[4] = __cosf(b.x + th1.x); q1[5] = __cosf(b.y + th1.y);
        q1[6] = __cosf(b.z + th1.z); q1[7] = __cosf(b.w + th1.w);
    } else {
#pragma unroll
        for (int i = 0; i < 8; ++i) q1[i] = 0.f;   // harmless: w=1 everywhere
    }

    *reinterpret_cast<float4*>(&qs[wl][0][lane][0]) = make_float4(q0[0], q0[1], q0[2], q0[3]);
    *reinterpret_cast<float4*>(&qs[wl][0][lane][4]) = make_float4(q0[4], q0[5], q0[6], q0[7]);
    *reinterpret_cast<float4*>(&qs[wl][1][lane][0]) = make_float4(q1[0], q1[1], q1[2], q1[3]);
    *reinterpret_cast<float4*>(&qs[wl][1][lane][4]) = make_float4(q1[4], q1[5], q1[6], q1[7]);
    __syncwarp();

    float ss0 = 0.f, ss1 = 0.f;
    float ac0[8] = {0.f, 0.f, 0.f, 0.f, 0.f, 0.f, 0.f, 0.f};
    float ac1[8] = {0.f, 0.f, 0.f, 0.f, 0.f, 0.f, 0.f, 0.f};

#pragma unroll 8
    for (int g = 0; g < NHEAD; ++g) {
        const float4 a0 = *reinterpret_cast<const float4*>(&qs[wl][0][g][0]);
        const float4 b0 = *reinterpret_cast<const float4*>(&qs[wl][0][g][4]);
        const float4 a1 = *reinterpret_cast<const float4*>(&qs[wl][1][g][0]);
        const float4 b1 = *reinterpret_cast<const float4*>(&qs[wl][1][g][4]);

        const float d0 = q0[0]*a0.x + q0[1]*a0.y + q0[2]*a0.z + q0[3]*a0.w
                       + q0[4]*b0.x + q0[5]*b0.y + q0[6]*b0.z + q0[7]*b0.w;
        const float d1 = q1[0]*a1.x + q1[1]*a1.y + q1[2]*a1.z + q1[3]*a1.w
                       + q1[4]*b1.x + q1[5]*b1.y + q1[6]*b1.z + q1[7]*b1.w;

        const float w0 = __expf(d0 * 0.35355339059327373f);
        const float w1 = __expf(d1 * 0.35355339059327373f);

        ss0 += w0;
        ac0[0] += w0 * a0.x; ac0[1] += w0 * a0.y; ac0[2] += w0 * a0.z; ac0[3] += w0 * a0.w;
        ac0[4] += w0 * b0.x; ac0[5] += w0 * b0.y; ac0[6] += w0 * b0.z; ac0[7] += w0 * b0.w;
        ss1 += w1;
        ac1[0] += w1 * a1.x; ac1[1] += w1 * a1.y; ac1[2] += w1 * a1.z; ac1[3] += w1 * a1.w;
        ac1[4] += w1 * b1.x; ac1[5] += w1 * b1.y; ac1[6] += w1 * b1.z; ac1[7] += w1 * b1.w;
    }

    {
        const float inv0 = 1.0f / ss0;
        uint4 h;
        h.x = packh2(ac0[0] * inv0, ac0[1] * inv0);
        h.y = packh2(ac0[2] * inv0, ac0[3] * inv0);
        h.z = packh2(ac0[4] * inv0, ac0[5] * inv0);
        h.w = packh2(ac0[6] * inv0, ac0[7] * inv0);
        *reinterpret_cast<uint4*>(g_mid + (size_t)tok0 * EDIM + lane * DK) = h;
    }
    if (v1) {
        const float inv1 = 1.0f / ss1;
        uint4 h;
        h.x = packh2(ac1[0] * inv1, ac1[1] * inv1);
        h.y = packh2(ac1[2] * inv1, ac1[3] * inv1);
        h.z = packh2(ac1[4] * inv1, ac1[5] * inv1);
        h.w = packh2(ac1[6] * inv1, ac1[7] * inv1);
        *reinterpret_cast<uint4*>(g_mid + (size_t)tok1 * EDIM + lane * DK) = h;
    }
}

// ---------------------------------------------------------------------------
// Kernel 2: C = A @ (Wh + Wl)^T + bias = A Wh^T + A Wl^T   (fp16 mma, fused)
// mma.sync.m16n8k16.row.col.f32.f16.f16.f32. Block 128x128, 8 k-chunks of 32.
// A tile loaded ONCE per chunk; both W products accumulate into the same acc.
// ---------------------------------------------------------------------------
#define GBM 128
#define GBN 128
#define GBK 32
#define KSTR 40
#define NKC  (EDIM / GBK)          // 8

__device__ __forceinline__ void mma16816h(float* d, const unsigned* a, const unsigned* b) {
    asm volatile(
        "mma.sync.aligned.m16n8k16.row.col.f32.f16.f16.f32 "
        "{%0,%1,%2,%3}, {%4,%5,%6,%7}, {%8,%9}, {%0,%1,%2,%3};\n"
        : "+f"(d[0]), "+f"(d[1]), "+f"(d[2]), "+f"(d[3])
        : "r"(a[0]), "r"(a[1]), "r"(a[2]), "r"(a[3]), "r"(b[0]), "r"(b[1]));
}

__global__ void __launch_bounds__(256) gemm_f16_kernel(
    const float* __restrict__ bias,
    float* __restrict__ C, int M)
{
    __shared__ __align__(16) __half As[GBM][KSTR];
    __shared__ __align__(16) __half Hs[GBN][KSTR];
    __shared__ __align__(16) __half Ls[GBN][KSTR];

    const int t    = threadIdx.x;
    const int warp = t >> 5;
    const int lane = t & 31;
    const int wm   = warp >> 2;      // 0..1  (M)
    const int wn   = warp & 3;       // 0..3  (N)
    const int gid  = lane >> 2;      // 0..7
    const int tig  = lane & 3;       // 0..3
    const int m0   = blockIdx.x * GBM;
    const int n0   = blockIdx.y * GBN;

    const int lr = t >> 2;           // 0..63 (rows; +64 second pass)
    const int lc = (t & 3) * 8;      // k offset (8 halves = 16B chunks)

    const __half* aB = g_mid + (size_t)m0 * EDIM;
    const __half* hB = g_Wh + (size_t)n0 * EDIM;
    const __half* lB = g_Wl + (size_t)n0 * EDIM;
    const bool av0 = (m0 + lr) < M;
    const bool av1 = (m0 + lr + 64) < M;

    float acc[4][4][4];
#pragma unroll
    for (int i = 0; i < 4; ++i)
#pragma unroll
        for (int j = 0; j < 4; ++j)
#pragma unroll
            for (int c = 0; c < 4; ++c) acc[i][j][c] = 0.f;

    const uint4 zed = make_uint4(0, 0, 0, 0);
    uint4 aR0, aR1, hR0, hR1, lR0, lR1;

    // prologue: chunk 0
    aR0 = av0 ? *reinterpret_cast<const uint4*>(aB + (size_t)lr * EDIM + lc) : zed;
    aR1 = av1 ? *reinterpret_cast<const uint4*>(aB + (size_t)(lr + 64) * EDIM + lc) : zed;
    hR0 = *reinterpret_cast<const uint4*>(hB + (size_t)lr * EDIM + lc);
    hR1 = *reinterpret_cast<const uint4*>(hB + (size_t)(lr + 64) * EDIM + lc);
    lR0 = *reinterpret_cast<const uint4*>(lB + (size_t)lr * EDIM + lc);
    lR1 = *reinterpret_cast<const uint4*>(lB + (size_t)(lr + 64) * EDIM + lc);

    for (int it = 0; it < NKC; ++it) {
        *reinterpret_cast<uint4*>(&As[lr][lc])      = aR0;
        *reinterpret_cast<uint4*>(&As[lr + 64][lc]) = aR1;
        *reinterpret_cast<uint4*>(&Hs[lr][lc])      = hR0;
        *reinterpret_cast<uint4*>(&Hs[lr + 64][lc]) = hR1;
        *reinterpret_cast<uint4*>(&Ls[lr][lc])      = lR0;
        *reinterpret_cast<uint4*>(&Ls[lr + 64][lc]) = lR1;
        __syncthreads();

        if (it + 1 < NKC) {
            const int kc = (it + 1) * GBK;
            aR0 = av0 ? *reinterpret_cast<const uint4*>(aB + (size_t)lr * EDIM + kc + lc) : zed;
            aR1 = av1 ? *reinterpret_cast<const uint4*>(aB + (size_t)(lr + 64) * EDIM + kc + lc) : zed;
            hR0 = *reinterpret_cast<const uint4*>(hB + (size_t)lr * EDIM + kc + lc);
            hR1 = *reinterpret_cast<const uint4*>(hB + (size_t)(lr + 64) * EDIM + kc + lc);
            lR0 = *reinterpret_cast<const uint4*>(lB + (size_t)lr * EDIM + kc + lc);
            lR1 = *reinterpret_cast<const uint4*>(lB + (size_t)(lr + 64) * EDIM + kc + lc);
        }

#pragma unroll
        for (int ks = 0; ks < 2; ++ks) {
            const int kk = ks * 16 + tig * 2;
            unsigned af[4][4], hf[4][2], lf[4][2];
#pragma unroll
            for (int fi = 0; fi < 4; ++fi) {
                const int r = wm * 64 + fi * 16 + gid;
                af[fi][0] = *reinterpret_cast<const unsigned*>(&As[r][kk]);
                af[fi][1] = *reinterpret_cast<const unsigned*>(&As[r + 8][kk]);
                af[fi][2] = *reinterpret_cast<const unsigned*>(&As[r][kk + 8]);
                af[fi][3] = *reinterpret_cast<const unsigned*>(&As[r + 8][kk + 8]);
            }
#pragma unroll
            for (int fj = 0; fj < 4; ++fj) {
                const int r = wn * 32 + fj * 8 + gid;
                hf[fj][0] = *reinterpret_cast<const unsigned*>(&Hs[r][kk]);
                hf[fj][1] = *reinterpret_cast<const unsigned*>(&Hs[r][kk + 8]);
                lf[fj][0] = *reinterpret_cast<const unsigned*>(&Ls[r][kk]);
                lf[fj][1] = *reinterpret_cast<const unsigned*>(&Ls[r][kk + 8]);
            }
#pragma unroll
            for (int fi = 0; fi < 4; ++fi)
#pragma unroll
                for (int fj = 0; fj < 4; ++fj) {
                    mma16816h(acc[fi][fj], af[fi], hf[fj]);
                    mma16816h(acc[fi][fj], af[fi], lf[fj]);
                }
        }
        __syncthreads();
    }

    // Epilogue: bias + fp32 store (float2 per fragment row).
#pragma unroll
    for (int fj = 0; fj < 4; ++fj) {
        const int col = n0 + wn * 32 + fj * 8 + tig * 2;
        const float2 bv = *reinterpret_cast<const float2*>(&bias[col]);
#pragma unroll
        for (int fi = 0; fi < 4; ++fi) {
            const int r0 = m0 + wm * 64 + fi * 16 + gid;
            if (r0 < M)
                *reinterpret_cast<float2*>(&C[(size_t)r0 * EDIM + col]) =
                    make_float2(acc[fi][fj][0] + bv.x, acc[fi][fj][1] + bv.y);
            const int r1 = r0 + 8;
            if (r1 < M)
                *reinterpret_cast<float2*>(&C[(size_t)r1 * EDIM + col]) =
                    make_float2(acc[fi][fj][2] + bv.x, acc[fi][fj][3] + bv.y);
        }
    }
}

// ---------------------------------------------------------------------------
extern "C" void kernel_launch(void* const* d_in, const int* in_sizes, int n_in,
                              void* d_out, int out_size)
{
    const float* x     = (const float*)d_in[0];
    const float* theta = (const float*)d_in[1];
    const float* W     = (const float*)d_in[2];
    const float* bias  = (const float*)d_in[3];
    float* out = (float*)d_out;

    int ntok = in_sizes[0] / EDIM;
    if (ntok > MAXTOK) ntok = MAXTOK;

    attn_kernel<<<(ntok + 7) / 8, 128>>>(x, theta, ntok);
    wconv_kernel<<<EDIM * EDIM / (256 * 8), 256>>>(W);

    dim3 grid((ntok + GBM - 1) / GBM, EDIM / GBN);
    gemm_f16_kernel<<<grid, 256>>>(bias, out, ntok);
}

// round 12
// speedup vs baseline: 1.7050x; 1.2662x over previous
#include <cuda_runtime.h>
#include <cuda_fp16.h>

#define NHEAD 32
#define DK    8
#define EDIM  256
#define MAXTOK (16 * 4096)

// Scratch (static __device__: no allocation, graph-capture safe).
// Attention output and W both in single fp16 (error budget verified:
// per-side fp16 rounding ~2.3e-4, combined ~3.3e-4 << 1e-3).
__device__ __half g_mid[(size_t)MAXTOK * EDIM];
__device__ __half g_Wh[EDIM * EDIM];

__device__ __forceinline__ unsigned packh2(float a, float b) {
    __half2 t = __floats2half2_rn(a, b);
    return *reinterpret_cast<unsigned*>(&t);
}

// ---------------------------------------------------------------------------
// Kernel 0: W (fp32) -> g_Wh (fp16). 65536 elems, 8 per thread.
// ---------------------------------------------------------------------------
__global__ void __launch_bounds__(256) wconv_kernel(const float* __restrict__ W)
{
    const int i = (blockIdx.x * 256 + threadIdx.x) * 8;
    float v[8];
    *reinterpret_cast<float4*>(v)     = *reinterpret_cast<const float4*>(W + i);
    *reinterpret_cast<float4*>(v + 4) = *reinterpret_cast<const float4*>(W + i + 4);
    uint4 h;
    h.x = packh2(v[0], v[1]); h.y = packh2(v[2], v[3]);
    h.z = packh2(v[4], v[5]); h.w = packh2(v[6], v[7]);
    *reinterpret_cast<uint4*>(g_Wh + i) = h;
}

// ---------------------------------------------------------------------------
// Kernel 1: per-token quantum attention. TWO tokens per warp, lane = head.
// Single fused pass per g: load q_g once -> dot -> exp -> accumulate.
//   out[h] = sum_g w[g] q[g] / sum_g w[g] -> single fp16 row into g_mid
// ---------------------------------------------------------------------------
__global__ void __launch_bounds__(128) attn_kernel(
    const float* __restrict__ x,
    const float* __restrict__ theta,
    int ntok)
{
    __shared__ __align__(16) float qs[4][2][NHEAD][DK];   // 8 KB
    const int wl   = threadIdx.x >> 5;
    const int lane = threadIdx.x & 31;
    const int tok0 = (blockIdx.x * 4 + wl) * 2;
    const int tok1 = tok0 + 1;
    if (tok0 >= ntok) return;              // uniform per warp
    const bool v1 = (tok1 < ntok);

    const float4 th0 = *reinterpret_cast<const float4*>(theta);
    const float4 th1 = *reinterpret_cast<const float4*>(theta + 4);

    float q0[8], q1[8];
    {
        const float4* xp = reinterpret_cast<const float4*>(
            x + (size_t)tok0 * EDIM + lane * DK);
        const float4 a = xp[0], b = xp[1];
        q0[0] = __cosf(a.x + th0.x); q0[1] = __cosf(a.y + th0.y);
        q0[2] = __cosf(a.z + th0.z); q0[3] = __cosf(a.w + th0.w);
        q0[4] = __cosf(b.x + th1.x); q0[5] = __cosf(b.y + th1.y);
        q0[6] = __cosf(b.z + th1.z); q0[7] = __cosf(b.w + th1.w);
    }
    if (v1) {
        const float4* xp = reinterpret_cast<const float4*>(
            x + (size_t)tok1 * EDIM + lane * DK);
        const float4 a = xp[0], b = xp[1];
        q1[0] = __cosf(a.x + th0.x); q1[1] = __cosf(a.y + th0.y);
        q1[2] = __cosf(a.z + th0.z); q1[3] = __cosf(a.w + th0.w);
        q1[4] = __cosf(b.x + th1.x); q1[5] = __cosf(b.y + th1.y);
        q1[6] = __cosf(b.z + th1.z); q1[7] = __cosf(b.w + th1.w);
    } else {
#pragma unroll
        for (int i = 0; i < 8; ++i) q1[i] = 0.f;   // harmless: w=1 everywhere
    }

    *reinterpret_cast<float4*>(&qs[wl][0][lane][0]) = make_float4(q0[0], q0[1], q0[2], q0[3]);
    *reinterpret_cast<float4*>(&qs[wl][0][lane][4]) = make_float4(q0[4], q0[5], q0[6], q0[7]);
    *reinterpret_cast<float4*>(&qs[wl][1][lane][0]) = make_float4(q1[0], q1[1], q1[2], q1[3]);
    *reinterpret_cast<float4*>(&qs[wl][1][lane][4]) = make_float4(q1[4], q1[5], q1[6], q1[7]);
    __syncwarp();

    float ss0 = 0.f, ss1 = 0.f;
    float ac0[8] = {0.f, 0.f, 0.f, 0.f, 0.f, 0.f, 0.f, 0.f};
    float ac1[8] = {0.f, 0.f, 0.f, 0.f, 0.f, 0.f, 0.f, 0.f};

#pragma unroll 8
    for (int g = 0; g < NHEAD; ++g) {
        const float4 a0 = *reinterpret_cast<const float4*>(&qs[wl][0][g][0]);
        const float4 b0 = *reinterpret_cast<const float4*>(&qs[wl][0][g][4]);
        const float4 a1 = *reinterpret_cast<const float4*>(&qs[wl][1][g][0]);
        const float4 b1 = *reinterpret_cast<const float4*>(&qs[wl][1][g][4]);

        const float d0 = q0[0]*a0.x + q0[1]*a0.y + q0[2]*a0.z + q0[3]*a0.w
                       + q0[4]*b0.x + q0[5]*b0.y + q0[6]*b0.z + q0[7]*b0.w;
        const float d1 = q1[0]*a1.x + q1[1]*a1.y + q1[2]*a1.z + q1[3]*a1.w
                       + q1[4]*b1.x + q1[5]*b1.y + q1[6]*b1.z + q1[7]*b1.w;

        const float w0 = __expf(d0 * 0.35355339059327373f);
        const float w1 = __expf(d1 * 0.35355339059327373f);

        ss0 += w0;
        ac0[0] += w0 * a0.x; ac0[1] += w0 * a0.y; ac0[2] += w0 * a0.z; ac0[3] += w0 * a0.w;
        ac0[4] += w0 * b0.x; ac0[5] += w0 * b0.y; ac0[6] += w0 * b0.z; ac0[7] += w0 * b0.w;
        ss1 += w1;
        ac1[0] += w1 * a1.x; ac1[1] += w1 * a1.y; ac1[2] += w1 * a1.z; ac1[3] += w1 * a1.w;
        ac1[4] += w1 * b1.x; ac1[5] += w1 * b1.y; ac1[6] += w1 * b1.z; ac1[7] += w1 * b1.w;
    }

    {
        const float inv0 = 1.0f / ss0;
        uint4 h;
        h.x = packh2(ac0[0] * inv0, ac0[1] * inv0);
        h.y = packh2(ac0[2] * inv0, ac0[3] * inv0);
        h.z = packh2(ac0[4] * inv0, ac0[5] * inv0);
        h.w = packh2(ac0[6] * inv0, ac0[7] * inv0);
        *reinterpret_cast<uint4*>(g_mid + (size_t)tok0 * EDIM + lane * DK) = h;
    }
    if (v1) {
        const float inv1 = 1.0f / ss1;
        uint4 h;
        h.x = packh2(ac1[0] * inv1, ac1[1] * inv1);
        h.y = packh2(ac1[2] * inv1, ac1[3] * inv1);
        h.z = packh2(ac1[4] * inv1, ac1[5] * inv1);
        h.w = packh2(ac1[6] * inv1, ac1[7] * inv1);
        *reinterpret_cast<uint4*>(g_mid + (size_t)tok1 * EDIM + lane * DK) = h;
    }
}

// ---------------------------------------------------------------------------
// Kernel 2: C = A @ Wh^T + bias, fp16 mma (single product per fragment pair).
// mma.sync.m16n8k16.row.col.f32.f16.f16.f32. Block 128x128, 8 k-chunks of 32.
// ---------------------------------------------------------------------------
#define GBM 128
#define GBN 128
#define GBK 32
#define KSTR 40
#define NKC  (EDIM / GBK)          // 8

__device__ __forceinline__ void mma16816h(float* d, const unsigned* a, const unsigned* b) {
    asm volatile(
        "mma.sync.aligned.m16n8k16.row.col.f32.f16.f16.f32 "
        "{%0,%1,%2,%3}, {%4,%5,%6,%7}, {%8,%9}, {%0,%1,%2,%3};\n"
        : "+f"(d[0]), "+f"(d[1]), "+f"(d[2]), "+f"(d[3])
        : "r"(a[0]), "r"(a[1]), "r"(a[2]), "r"(a[3]), "r"(b[0]), "r"(b[1]));
}

__global__ void __launch_bounds__(256) gemm_f16_kernel(
    const float* __restrict__ bias,
    float* __restrict__ C, int M)
{
    __shared__ __align__(16) __half As[GBM][KSTR];
    __shared__ __align__(16) __half Hs[GBN][KSTR];

    const int t    = threadIdx.x;
    const int warp = t >> 5;
    const int lane = t & 31;
    const int wm   = warp >> 2;      // 0..1  (M)
    const int wn   = warp & 3;       // 0..3  (N)
    const int gid  = lane >> 2;      // 0..7
    const int tig  = lane & 3;       // 0..3
    const int m0   = blockIdx.x * GBM;
    const int n0   = blockIdx.y * GBN;

    const int lr = t >> 2;           // 0..63 (rows; +64 second pass)
    const int lc = (t & 3) * 8;      // k offset (8 halves = 16B chunks)

    const __half* aB = g_mid + (size_t)m0 * EDIM;
    const __half* hB = g_Wh + (size_t)n0 * EDIM;
    const bool av0 = (m0 + lr) < M;
    const bool av1 = (m0 + lr + 64) < M;

    float acc[4][4][4];
#pragma unroll
    for (int i = 0; i < 4; ++i)
#pragma unroll
        for (int j = 0; j < 4; ++j)
#pragma unroll
            for (int c = 0; c < 4; ++c) acc[i][j][c] = 0.f;

    const uint4 zed = make_uint4(0, 0, 0, 0);
    uint4 aR0, aR1, hR0, hR1;

    // prologue: chunk 0
    aR0 = av0 ? *reinterpret_cast<const uint4*>(aB + (size_t)lr * EDIM + lc) : zed;
    aR1 = av1 ? *reinterpret_cast<const uint4*>(aB + (size_t)(lr + 64) * EDIM + lc) : zed;
    hR0 = *reinterpret_cast<const uint4*>(hB + (size_t)lr * EDIM + lc);
    hR1 = *reinterpret_cast<const uint4*>(hB + (size_t)(lr + 64) * EDIM + lc);

    for (int it = 0; it < NKC; ++it) {
        *reinterpret_cast<uint4*>(&As[lr][lc])      = aR0;
        *reinterpret_cast<uint4*>(&As[lr + 64][lc]) = aR1;
        *reinterpret_cast<uint4*>(&Hs[lr][lc])      = hR0;
        *reinterpret_cast<uint4*>(&Hs[lr + 64][lc]) = hR1;
        __syncthreads();

        if (it + 1 < NKC) {
            const int kc = (it + 1) * GBK;
            aR0 = av0 ? *reinterpret_cast<const uint4*>(aB + (size_t)lr * EDIM + kc + lc) : zed;
            aR1 = av1 ? *reinterpret_cast<const uint4*>(aB + (size_t)(lr + 64) * EDIM + kc + lc) : zed;
            hR0 = *reinterpret_cast<const uint4*>(hB + (size_t)lr * EDIM + kc + lc);
            hR1 = *reinterpret_cast<const uint4*>(hB + (size_t)(lr + 64) * EDIM + kc + lc);
        }

#pragma unroll
        for (int ks = 0; ks < 2; ++ks) {
            const int kk = ks * 16 + tig * 2;
            unsigned af[4][4], hf[4][2];
#pragma unroll
            for (int fi = 0; fi < 4; ++fi) {
                const int r = wm * 64 + fi * 16 + gid;
                af[fi][0] = *reinterpret_cast<const unsigned*>(&As[r][kk]);
                af[fi][1] = *reinterpret_cast<const unsigned*>(&As[r + 8][kk]);
                af[fi][2] = *reinterpret_cast<const unsigned*>(&As[r][kk + 8]);
                af[fi][3] = *reinterpret_cast<const unsigned*>(&As[r + 8][kk + 8]);
            }
#pragma unroll
            for (int fj = 0; fj < 4; ++fj) {
                const int r = wn * 32 + fj * 8 + gid;
                hf[fj][0] = *reinterpret_cast<const unsigned*>(&Hs[r][kk]);
                hf[fj][1] = *reinterpret_cast<const unsigned*>(&Hs[r][kk + 8]);
            }
#pragma unroll
            for (int fi = 0; fi < 4; ++fi)
#pragma unroll
                for (int fj = 0; fj < 4; ++fj)
                    mma16816h(acc[fi][fj], af[fi], hf[fj]);
        }
        __syncthreads();
    }

    // Epilogue: bias + fp32 store (float2 per fragment row).
#pragma unroll
    for (int fj = 0; fj < 4; ++fj) {
        const int col = n0 + wn * 32 + fj * 8 + tig * 2;
        const float2 bv = *reinterpret_cast<const float2*>(&bias[col]);
#pragma unroll
        for (int fi = 0; fi < 4; ++fi) {
            const int r0 = m0 + wm * 64 + fi * 16 + gid;
            if (r0 < M)
                *reinterpret_cast<float2*>(&C[(size_t)r0 * EDIM + col]) =
                    make_float2(acc[fi][fj][0] + bv.x, acc[fi][fj][1] + bv.y);
            const int r1 = r0 + 8;
            if (r1 < M)
                *reinterpret_cast<float2*>(&C[(size_t)r1 * EDIM + col]) =
                    make_float2(acc[fi][fj][2] + bv.x, acc[fi][fj][3] + bv.y);
        }
    }
}

// ---------------------------------------------------------------------------
extern "C" void kernel_launch(void* const* d_in, const int* in_sizes, int n_in,
                              void* d_out, int out_size)
{
    const float* x     = (const float*)d_in[0];
    const float* theta = (const float*)d_in[1];
    const float* W     = (const float*)d_in[2];
    const float* bias  = (const float*)d_in[3];
    float* out = (float*)d_out;

    int ntok = in_sizes[0] / EDIM;
    if (ntok > MAXTOK) ntok = MAXTOK;

    attn_kernel<<<(ntok + 7) / 8, 128>>>(x, theta, ntok);
    wconv_kernel<<<EDIM * EDIM / (256 * 8), 256>>>(W);

    dim3 grid((ntok + GBM - 1) / GBM, EDIM / GBN);
    gemm_f16_kernel<<<grid, 256>>>(bias, out, ntok);
}